// round 7
// baseline (speedup 1.0000x reference)
#include <cuda_runtime.h>
#include <cuda_bf16.h>
#include <cstddef>

// Fused YOLOv3 decode, all 3 scales, one PERSISTENT kernel.
// R6 showed occ=59.6% but DRAM stuck at 49%: grid=1331 at 6 blocks/SM is 1.5
// waves -> wave 2 runs the chip half-empty. This round: grid-stride loop with
// exactly 148*6 = 888 blocks so there is a single wave and all blocks drain
// together. Item mapping unchanged: item = a*cells + cell, lanes on
// consecutive cells -> fully coalesced channel loads.

__device__ __forceinline__ float sigf(float x) { return 1.0f / (1.0f + __expf(-x)); }

__global__ __launch_bounds__(256, 6)
void yolo_decode_r7(const float* __restrict__ o13,
                    const float* __restrict__ o26,
                    const float* __restrict__ o52,
                    const float* __restrict__ a13,
                    const float* __restrict__ a26,
                    const float* __restrict__ a52,
                    const float* __restrict__ threshp,
                    const int*   __restrict__ casep,
                    float* __restrict__ boxes,   // [N,6]
                    float* __restrict__ mask,    // [N]
                    int B, int cells)
{
    // hoisted scalars (uniform across the whole launch)
    const int iv = __ldg(casep);
    const float case_f = (iv > 0 && iv < 1000000) ? (float)iv : __int_as_float(iv);
    const float inv_case = 1.0f / case_f;
    const float thresh = __ldg(threshp);

    const int C13 = B * 13 * 13;
    const int C26 = B * 26 * 26;

    const int nitems = 3 * cells;
    const int stride = gridDim.x * blockDim.x;

    for (int tid = blockIdx.x * blockDim.x + threadIdx.x; tid < nitems; tid += stride)
    {
        const int a    = tid / cells;       // anchor 0..2
        const int cell = tid - a * cells;   // global cell id

        // Resolve scale from cell id
        const float* in; const float* anch;
        int S, local, rowoff; float t;
        if (cell < C13)            { in = o13; anch = a13; S = 13; local = cell;              rowoff = 0;               t = 32.0f; }
        else if (cell < C13 + C26) { in = o26; anch = a26; S = 26; local = cell - C13;        rowoff = C13 * 3;         t = 16.0f; }
        else                       { in = o52; anch = a52; S = 52; local = cell - C13 - C26;  rowoff = (C13 + C26) * 3; t = 8.0f;  }

        const int HW  = S * S;
        const int b   = local / HW;
        const int pos = local - b * HW;
        const int h   = pos / S;
        const int w   = pos - h * S;
        const float scale = t * inv_case;

        const float* p = in + (size_t)(b * 255 + a * 85) * HW + pos;

        const float o0 = __ldg(p);
        const float o1 = __ldg(p + HW);
        const float o2 = __ldg(p + 2 * HW);
        const float o3 = __ldg(p + 3 * HW);
        const float o4 = __ldg(p + 4 * HW);

        // Argmax over 80 class logits, 10-wide load batches.
        // Strict '>' keeps FIRST max (jnp.argmax tie rule).
        float maxv = -3.4e38f;
        int   cls  = 0;
        const float* pc = p + 5 * HW;
        #pragma unroll
        for (int d0 = 0; d0 < 80; d0 += 10) {
            float v[10];
            #pragma unroll
            for (int i = 0; i < 10; ++i)
                v[i] = __ldg(pc + (d0 + i) * HW);
            #pragma unroll
            for (int i = 0; i < 10; ++i)
                if (v[i] > maxv) { maxv = v[i]; cls = d0 + i; }
        }

        const float prob = sigf(o0);
        const float cx = ((float)w + o1) * scale;
        const float cy = ((float)h + o2) * scale;
        const float bw = __ldg(anch + a * 2 + 0) * __expf(o3) * inv_case;
        const float bh = __ldg(anch + a * 2 + 1) * __expf(o4) * inv_case;

        const int row = rowoff + local * 3 + a;
        float* r = boxes + (size_t)row * 6;
        r[0] = prob;
        r[1] = cx;
        r[2] = cy;
        r[3] = bw;
        r[4] = bh;
        r[5] = (float)cls;

        mask[row] = (o0 > thresh) ? 1.0f : 0.0f;
    }
}

extern "C" void kernel_launch(void* const* d_in, const int* in_sizes, int n_in,
                              void* d_out, int out_size)
{
    const float* o13 = (const float*)d_in[0];
    const float* o26 = (const float*)d_in[1];
    const float* o52 = (const float*)d_in[2];
    const float* a13 = (const float*)d_in[3];
    const float* a26 = (const float*)d_in[4];
    const float* a52 = (const float*)d_in[5];
    const float* th  = (const float*)d_in[6];
    const int*   cs  = (const int*)  d_in[7];

    const int B = in_sizes[0] / (255 * 13 * 13);

    const int C13 = B * 13 * 13;
    const int C26 = B * 26 * 26;
    const int C52 = B * 52 * 52;
    const int cells = C13 + C26 + C52;
    const int N = cells * 3;

    float* boxes = (float*)d_out;                   // [N,6]
    float* mask  = (float*)d_out + (size_t)N * 6;   // [N]

    // Single wave: 148 SMs * 6 resident blocks (launch_bounds(256,6)).
    const int TPB  = 256;
    const int grid = 148 * 6;
    yolo_decode_r7<<<grid, TPB>>>(
        o13, o26, o52, a13, a26, a52, th, cs, boxes, mask, B, cells);
}